// round 9
// baseline (speedup 1.0000x reference)
#include <cuda_runtime.h>
#include <math.h>

// ---------------------------------------------------------------- dims
#define Bb    128
#define Ss    512
#define Hh    1024
#define MIDm  512
#define FEATf 576

#define BH    131072      // B*H
#define BMID  65536       // B*MID
#define B4H   524288      // B*4H
#define NX    37748736    // S*B*FEAT

// ---------------------------------------------------------------- scratch (floats)
#define OFF_X     0
#define OFF_H1    (OFF_X   + NX)
#define OFF_C1    (OFF_H1  + BH)
#define OFF_H2    (OFF_C1  + BH)
#define OFF_C2    (OFF_H2  + BH)
#define OFF_X2    (OFF_C2  + BH)
#define OFF_ZBA   (OFF_X2  + BH)
#define OFF_ZBB0  (OFF_ZBA + BMID)
#define OFF_ZBB1  (OFF_ZBB0+ BMID)
#define OFF_M1A   (OFF_ZBB1+ BMID)
#define OFF_M1B0  (OFF_M1A + BH)
#define OFF_M1B1  (OFF_M1B0+ BH)
#define OFF_Z1A   (OFF_M1B1+ BH)
#define OFF_Z1B0  (OFF_Z1A + B4H)
#define OFF_Z1B1  (OFF_Z1B0+ B4H)
#define OFF_M2A0  (OFF_Z1B1+ B4H)
#define OFF_M2A1  (OFF_M2A0+ BH)
#define OFF_M2B0  (OFF_M2A1+ BH)
#define OFF_M2B1  (OFF_M2B0+ BH)
#define OFF_Z2A0  (OFF_M2B1+ BH)
#define OFF_Z2A1  (OFF_Z2A0+ B4H)
#define OFF_Z2B0  (OFF_Z2A1+ B4H)
#define OFF_Z2B1  (OFF_Z2B0+ B4H)
#define OFF_SBUF  (OFF_Z2B1+ B4H)
#define SCRATCH_TOTAL (OFF_SBUF + 128)

__device__ __align__(16) float g_scratch[SCRATCH_TOTAL];
__device__ unsigned g_bar_count = 0;
__device__ unsigned g_bar_gen   = 0;
__device__ unsigned g_work      = 0;
__device__ float    g_flag      = 0.0f;

// ---------------------------------------------------------------- output layout
#define OUT_H2F   67108864            // B*S*H
#define OUT_C2F   (OUT_H2F + BH)
#define OUT_FLAGS (OUT_C2F + BH)

__device__ __forceinline__ float sigm(float x) { return 1.0f / (1.0f + expf(-x)); }

// ---------------------------------------------------------------- grid barrier
// On exit: g_work == 0 and all pre-barrier global writes are visible.
__device__ __forceinline__ void grid_barrier(unsigned nct)
{
    __syncthreads();
    if (threadIdx.x == 0) {
        unsigned gen = *(volatile unsigned*)&g_bar_gen;
        __threadfence();
        unsigned prev = atomicAdd(&g_bar_count, 1u);
        if (prev == nct - 1u) {
            *(volatile unsigned*)&g_work = 0u;
            *(volatile unsigned*)&g_bar_count = 0u;
            __threadfence();
            *(volatile unsigned*)&g_bar_gen = gen + 1u;
        } else {
            while (*(volatile unsigned*)&g_bar_gen == gen) { __nanosleep(64); }
        }
        __threadfence();   // acquire
    }
    __syncthreads();
}

// ---------------------------------------------------------------- tile GEMM
// out[0:128, n0:n0+64] = Aeff[0:128, k0:k0+klen] @ W[n0:n0+64, k0:k0+klen]^T
//   LM=0: Aeff = A     LM=1: Aeff = A .* (A2 + A3)    LM=2: Aeff = (A+A2) .* (A3+A4)
// 256 threads, 8x4 microtile, k-chunks of 32, double-buffered smem.
#define SA_STRIDE 136
#define SW_STRIDE 72
#define SA_BUF    4352   // 32*136
#define SW_BUF    2304   // 32*72

template<int LM>
__device__ __forceinline__ void load_regs(
    const float* __restrict__ A, const float* __restrict__ A2,
    const float* __restrict__ A3, const float* __restrict__ A4,
    int lda, const float* __restrict__ W, int ldw,
    int kbase, int n0, int tid, float4* pa, float4* pw)
{
    const int lrow = tid >> 1, half = tid & 1;
#pragma unroll
    for (int it = 0; it < 4; it++) {
        const int kq = kbase + half * 16 + it * 4;
        float4 a = *(const float4*)(A + (size_t)lrow * lda + kq);
        if (LM == 1) {
            float4 b = *(const float4*)(A2 + (size_t)lrow * lda + kq);
            float4 c = *(const float4*)(A3 + (size_t)lrow * lda + kq);
            a.x = a.x * (b.x + c.x); a.y = a.y * (b.y + c.y);
            a.z = a.z * (b.z + c.z); a.w = a.w * (b.w + c.w);
        } else if (LM == 2) {
            float4 b = *(const float4*)(A2 + (size_t)lrow * lda + kq);
            float4 c = *(const float4*)(A3 + (size_t)lrow * lda + kq);
            float4 d = *(const float4*)(A4 + (size_t)lrow * lda + kq);
            a.x = (a.x + b.x) * (c.x + d.x); a.y = (a.y + b.y) * (c.y + d.y);
            a.z = (a.z + b.z) * (c.z + d.z); a.w = (a.w + b.w) * (c.w + d.w);
        }
        pa[it] = a;
    }
    const int wrow = tid >> 2, wq = tid & 3;
#pragma unroll
    for (int it = 0; it < 2; it++) {
        const int kq = kbase + (wq + it * 4) * 4;
        pw[it] = *(const float4*)(W + (size_t)(n0 + wrow) * ldw + kq);
    }
}

__device__ __forceinline__ void store_smem(float* sA, float* sW, int tid,
                                           const float4* pa, const float4* pw)
{
    const int lrow = tid >> 1, half = tid & 1;
#pragma unroll
    for (int it = 0; it < 4; it++) {
        const int kk = half * 16 + it * 4;
        sA[(kk + 0) * SA_STRIDE + lrow] = pa[it].x;
        sA[(kk + 1) * SA_STRIDE + lrow] = pa[it].y;
        sA[(kk + 2) * SA_STRIDE + lrow] = pa[it].z;
        sA[(kk + 3) * SA_STRIDE + lrow] = pa[it].w;
    }
    const int wrow = tid >> 2, wq = tid & 3;
#pragma unroll
    for (int it = 0; it < 2; it++) {
        const int kk = (wq + it * 4) * 4;
        sW[(kk + 0) * SW_STRIDE + wrow] = pw[it].x;
        sW[(kk + 1) * SW_STRIDE + wrow] = pw[it].y;
        sW[(kk + 2) * SW_STRIDE + wrow] = pw[it].z;
        sW[(kk + 3) * SW_STRIDE + wrow] = pw[it].w;
    }
}

template<int LM>
__device__ void gemm_tile(float* sA, float* sW,
    const float* __restrict__ A, const float* __restrict__ A2,
    const float* __restrict__ A3, const float* __restrict__ A4,
    int lda, const float* __restrict__ W, int ldw,
    int k0, int klen, int n0, float* __restrict__ outp, int ldo)
{
    const int tid = threadIdx.x;
    const int tm = tid >> 4;   // 0..15 (8 rows each)
    const int tn = tid & 15;   // 0..15 (4 cols each)

    float4 acc[8];
#pragma unroll
    for (int i = 0; i < 8; i++) acc[i] = make_float4(0.f, 0.f, 0.f, 0.f);

    float4 pa[4], pw[2];
    load_regs<LM>(A, A2, A3, A4, lda, W, ldw, k0, n0, tid, pa, pw);
    __syncthreads();                 // previous user done with smem
    store_smem(sA, sW, tid, pa, pw);
    __syncthreads();

    const int nch = klen >> 5;
    for (int c = 0; c < nch; c++) {
        const float* cA = sA + (c & 1) * SA_BUF;
        const float* cW = sW + (c & 1) * SW_BUF;
        if (c + 1 < nch)
            load_regs<LM>(A, A2, A3, A4, lda, W, ldw, k0 + (c + 1) * 32, n0, tid, pa, pw);
#pragma unroll
        for (int k = 0; k < 32; k++) {
            float4 a0 = *(const float4*)&cA[k * SA_STRIDE + tm * 8];
            float4 a1 = *(const float4*)&cA[k * SA_STRIDE + tm * 8 + 4];
            float4 w  = *(const float4*)&cW[k * SW_STRIDE + tn * 4];
#define FMA4_(av, idx) acc[idx].x += (av) * w.x; acc[idx].y += (av) * w.y; \
                       acc[idx].z += (av) * w.z; acc[idx].w += (av) * w.w;
            FMA4_(a0.x, 0) FMA4_(a0.y, 1) FMA4_(a0.z, 2) FMA4_(a0.w, 3)
            FMA4_(a1.x, 4) FMA4_(a1.y, 5) FMA4_(a1.z, 6) FMA4_(a1.w, 7)
#undef FMA4_
        }
        if (c + 1 < nch)
            store_smem(sA + ((c + 1) & 1) * SA_BUF, sW + ((c + 1) & 1) * SW_BUF, tid, pa, pw);
        __syncthreads();
    }

#pragma unroll
    for (int i = 0; i < 8; i++)
        *(float4*)&outp[(size_t)(tm * 8 + i) * ldo + n0 + tn * 4] = acc[i];
}

// ---------------------------------------------------------------- boundary (one CTA)
__device__ void boundary_tile(const float* __restrict__ zba,
                              const float* __restrict__ zbb0,
                              const float* __restrict__ zbb1,
                              const float* __restrict__ b_bd,
                              const float* __restrict__ vs,
                              float* __restrict__ sbuf,
                              float* __restrict__ out, int t, int out_size)
{
    const int tid = threadIdx.x, w = tid >> 5, lane = tid & 31;
    for (int b = w; b < Bb; b += 8) {
        float sum = 0.0f;
        for (int j = lane; j < MIDm; j += 32) {
            float z = zba[b * MIDm + j] + zbb0[b * MIDm + j] + zbb1[b * MIDm + j] + b_bd[j];
            sum += z * vs[j];
        }
#pragma unroll
        for (int o = 16; o > 0; o >>= 1) sum += __shfl_down_sync(0xffffffffu, sum, o);
        if (lane == 0) {
            float p = 1.0f / (1.0f + expf(-sum));
            float bin = (p > 0.5f) ? 1.0f : 0.0f;
            float sv = p + (bin - p);
            sbuf[b] = sv;
            if (b == 0) {
                g_flag = sv;
                if (OUT_FLAGS + t < out_size) out[OUT_FLAGS + t] = sv;
            }
        }
    }
}

// ---------------------------------------------------------------- persistent kernel
__global__ void __launch_bounds__(256, 1)
enc_persistent(const float* __restrict__ Wsi,  const float* __restrict__ Wsh,
               const float* __restrict__ b_bd, const float* __restrict__ vs,
               const float* __restrict__ Wmx1, const float* __restrict__ Wmh1,
               const float* __restrict__ Wih1, const float* __restrict__ Whh1,
               const float* __restrict__ b1,
               const float* __restrict__ Wmx2, const float* __restrict__ Wmh2,
               const float* __restrict__ Wih2, const float* __restrict__ Whh2,
               const float* __restrict__ b2,
               float* __restrict__ out, int out_size)
{
    extern __shared__ float smem[];
    float* sA = smem;
    float* sW = smem + 2 * SA_BUF;
    __shared__ int s_id;

    const unsigned nct = gridDim.x;
    const int bid = blockIdx.x, tid = threadIdx.x;
    float* base = g_scratch;
    const float* X = base + OFF_X;
    float* h1 = base + OFF_H1;  float* c1 = base + OFF_C1;
    float* h2 = base + OFF_H2;  float* c2 = base + OFF_C2;
    float* x2 = base + OFF_X2;
    float* zba  = base + OFF_ZBA;  float* zbb0 = base + OFF_ZBB0; float* zbb1 = base + OFF_ZBB1;
    float* m1a  = base + OFF_M1A;  float* m1b0 = base + OFF_M1B0; float* m1b1 = base + OFF_M1B1;
    float* z1a  = base + OFF_Z1A;  float* z1b0 = base + OFF_Z1B0; float* z1b1 = base + OFF_Z1B1;
    float* m2a0 = base + OFF_M2A0; float* m2a1 = base + OFF_M2A1;
    float* m2b0 = base + OFF_M2B0; float* m2b1 = base + OFF_M2B1;
    float* z2a0 = base + OFF_Z2A0; float* z2a1 = base + OFF_Z2A1;
    float* z2b0 = base + OFF_Z2B0; float* z2b1 = base + OFF_Z2B1;
    float* sbuf = base + OFF_SBUF;

    // CTA-wide tile grab: one atomic per CTA, broadcast via shared.
    // First __syncthreads makes the write visible; second orders the read
    // before the next iteration's overwrite (work bodies may lack syncs).
#define GRAB_TILE(id_)  { if (tid == 0) s_id = (int)atomicAdd(&g_work, 1u); \
                          __syncthreads(); (id_) = s_id; __syncthreads(); }

    // ---- init: zero recurrent state (h1,c1,h2,c2 contiguous) ----
    for (int i = bid * 256 + tid; i < 4 * BH; i += nct * 256) h1[i] = 0.0f;
    grid_barrier(nct);

    for (int t = 0; t < Ss; t++) {
        const float* xt = X + (size_t)t * Bb * FEATf;

        // ================= Phase A : 136 tiles =================
        for (;;) {
            int id; GRAB_TILE(id);
            if (id >= 136) break;
            if      (id < 8)    gemm_tile<0>(sA, sW, xt, 0, 0, 0, FEATf, Wsi,  FEATf, 0,   FEATf, id * 64,        zba,  MIDm);
            else if (id < 16)   gemm_tile<0>(sA, sW, h1, 0, 0, 0, Hh,    Wsh,  Hh,    0,   512,   (id - 8) * 64,  zbb0, MIDm);
            else if (id < 24)   gemm_tile<0>(sA, sW, h1, 0, 0, 0, Hh,    Wsh,  Hh,    512, 512,   (id - 16) * 64, zbb1, MIDm);
            else if (id < 40)   gemm_tile<0>(sA, sW, xt, 0, 0, 0, FEATf, Wmx1, FEATf, 0,   FEATf, (id - 24) * 64, m1a,  Hh);
            else if (id < 56)   gemm_tile<0>(sA, sW, h1, 0, 0, 0, Hh,    Wmh1, Hh,    0,   512,   (id - 40) * 64, m1b0, Hh);
            else if (id < 72)   gemm_tile<0>(sA, sW, h1, 0, 0, 0, Hh,    Wmh1, Hh,    512, 512,   (id - 56) * 64, m1b1, Hh);
            else                gemm_tile<0>(sA, sW, xt, 0, 0, 0, FEATf, Wih1, FEATf, 0,   FEATf, (id - 72) * 64, z1a,  4096);
        }
        grid_barrier(nct);

        // ================= Phase B : 129 tiles =================
        for (;;) {
            int id; GRAB_TILE(id);
            if (id >= 129) break;
            if      (id < 64)  gemm_tile<1>(sA, sW, m1a, m1b0, m1b1, 0, Hh, Whh1, Hh, 0,   512, id * 64,        z1b0, 4096);
            else if (id < 128) gemm_tile<1>(sA, sW, m1a, m1b0, m1b1, 0, Hh, Whh1, Hh, 512, 512, (id - 64) * 64, z1b1, 4096);
            else               boundary_tile(zba, zbb0, zbb1, b_bd, vs, sbuf, out, t, out_size);
        }
        grid_barrier(nct);

        // ================= Phase C : gates1 =================
        for (int idx = bid * 256 + tid; idx < BH; idx += nct * 256) {
            const int b = idx >> 10, h = idx & 1023;
            const size_t zb = (size_t)b * 4096;
            float iz = z1a[zb + h]        + z1b0[zb + h]        + z1b1[zb + h]        + b1[h];
            float fz = z1a[zb + 1024 + h] + z1b0[zb + 1024 + h] + z1b1[zb + 1024 + h] + b1[1024 + h];
            float gz = z1a[zb + 2048 + h] + z1b0[zb + 2048 + h] + z1b1[zb + 2048 + h] + b1[2048 + h];
            float oz = z1a[zb + 3072 + h] + z1b0[zb + 3072 + h] + z1b1[zb + 3072 + h] + b1[3072 + h];
            float cn = sigm(fz) * c1[idx] + sigm(iz) * tanhf(gz);
            float hn = sigm(oz) * tanhf(cn);
            float sv = sbuf[b];
            float om = 1.0f - sv;
            x2[idx] = hn * sv;
            h1[idx] = hn * om;
            c1[idx] = cn * om;
        }
        grid_barrier(nct);

        const float fl = *(volatile float*)&g_flag;

        if (fl > 0.5f) {
            // ================= Phase D : 192 tiles =================
            for (;;) {
                int id; GRAB_TILE(id);
                if (id >= 192) break;
                if      (id < 16)  gemm_tile<0>(sA, sW, x2, 0, 0, 0, Hh, Wmx2, Hh, 0,   512, id * 64,         m2a0, Hh);
                else if (id < 32)  gemm_tile<0>(sA, sW, x2, 0, 0, 0, Hh, Wmx2, Hh, 512, 512, (id - 16) * 64,  m2a1, Hh);
                else if (id < 48)  gemm_tile<0>(sA, sW, h2, 0, 0, 0, Hh, Wmh2, Hh, 0,   512, (id - 32) * 64,  m2b0, Hh);
                else if (id < 64)  gemm_tile<0>(sA, sW, h2, 0, 0, 0, Hh, Wmh2, Hh, 512, 512, (id - 48) * 64,  m2b1, Hh);
                else if (id < 128) gemm_tile<0>(sA, sW, x2, 0, 0, 0, Hh, Wih2, Hh, 0,   512, (id - 64) * 64,  z2a0, 4096);
                else               gemm_tile<0>(sA, sW, x2, 0, 0, 0, Hh, Wih2, Hh, 512, 512, (id - 128) * 64, z2a1, 4096);
            }
            grid_barrier(nct);

            // ================= Phase E : 128 tiles =================
            for (;;) {
                int id; GRAB_TILE(id);
                if (id >= 128) break;
                if (id < 64) gemm_tile<2>(sA, sW, m2a0, m2a1, m2b0, m2b1, Hh, Whh2, Hh, 0,   512, id * 64,        z2b0, 4096);
                else         gemm_tile<2>(sA, sW, m2a0, m2a1, m2b0, m2b1, Hh, Whh2, Hh, 512, 512, (id - 64) * 64, z2b1, 4096);
            }
            grid_barrier(nct);
        }

        // ================= Phase F : gates2 / copy =================
        for (int idx = bid * 256 + tid; idx < BH; idx += nct * 256) {
            const int b = idx >> 10, h = idx & 1023;
            const size_t oidx = ((size_t)b * Ss + t) * Hh + h;
            if (fl > 0.5f) {
                const size_t zb = (size_t)b * 4096;
                float iz = z2a0[zb + h]        + z2a1[zb + h]        + z2b0[zb + h]        + z2b1[zb + h]        + b2[h];
                float fz = z2a0[zb + 1024 + h] + z2a1[zb + 1024 + h] + z2b0[zb + 1024 + h] + z2b1[zb + 1024 + h] + b2[1024 + h];
                float gz = z2a0[zb + 2048 + h] + z2a1[zb + 2048 + h] + z2b0[zb + 2048 + h] + z2b1[zb + 2048 + h] + b2[2048 + h];
                float oz = z2a0[zb + 3072 + h] + z2a1[zb + 3072 + h] + z2b0[zb + 3072 + h] + z2b1[zb + 3072 + h] + b2[3072 + h];
                float cn = sigm(fz) * c2[idx] + sigm(iz) * tanhf(gz);
                float hn = sigm(oz) * tanhf(cn);
                h2[idx] = hn;
                c2[idx] = cn;
                out[oidx] = hn;
            } else {
                out[oidx] = h2[idx];
            }
        }
        grid_barrier(nct);
    }

    // ---- tail: final states ----
    for (int idx = bid * 256 + tid; idx < BH; idx += nct * 256) {
        if (OUT_H2F + idx < out_size) out[OUT_H2F + idx] = h2[idx];
        if (OUT_C2F + idx < out_size) out[OUT_C2F + idx] = c2[idx];
    }
#undef GRAB_TILE
}

// ---------------------------------------------------------------- embedding gather
__global__ void gather_kernel(const int* __restrict__ enc,
                              const int* __restrict__ xenc,
                              const float* __restrict__ wemb,
                              const float* __restrict__ xemb,
                              float* __restrict__ X)
{
    int idx = blockIdx.x * 256 + threadIdx.x;
    if (idx >= NX) return;
    int f  = idx % FEATf;
    int sb = idx / FEATf;
    int b  = sb % Bb;
    int s  = sb / Bb;
    float v;
    if (f < 512) {
        int id = enc[b * Ss + s];
        v = wemb[(size_t)id * 512 + f];
    } else {
        int id = xenc[b * Ss + s];
        v = xemb[id * 64 + (f - 512)];
    }
    X[idx] = v;
}

// ----------------------------------------------------------------
extern "C" void kernel_launch(void* const* d_in, const int* in_sizes, int n_in,
                              void* d_out, int out_size)
{
    const int*   enc  = (const int*)d_in[0];
    const int*   xenc = (const int*)d_in[1];
    const float* wemb = (const float*)d_in[2];
    const float* xemb = (const float*)d_in[3];
    const float* Wsi  = (const float*)d_in[4];
    const float* Wsh  = (const float*)d_in[5];
    const float* b_bd = (const float*)d_in[6];
    const float* vs   = (const float*)d_in[7];
    const float* Wmx1 = (const float*)d_in[8];
    const float* Wmh1 = (const float*)d_in[9];
    const float* Wih1 = (const float*)d_in[10];
    const float* Whh1 = (const float*)d_in[11];
    const float* b1   = (const float*)d_in[12];
    const float* Wmx2 = (const float*)d_in[13];
    const float* Wmh2 = (const float*)d_in[14];
    const float* Wih2 = (const float*)d_in[15];
    const float* Whh2 = (const float*)d_in[16];
    const float* b2   = (const float*)d_in[17];
    float* out = (float*)d_out;

    float* base = nullptr;
    cudaGetSymbolAddress((void**)&base, g_scratch);
    float* X = base + OFF_X;

    gather_kernel<<<(NX + 255) / 256, 256>>>(enc, xenc, wemb, xemb, X);

    int nsm = 148;
    cudaDeviceGetAttribute(&nsm, cudaDevAttrMultiProcessorCount, 0);

    const int smem_bytes = (2 * SA_BUF + 2 * SW_BUF) * 4;   // 53248
    cudaFuncSetAttribute(enc_persistent, cudaFuncAttributeMaxDynamicSharedMemorySize, smem_bytes);

    enc_persistent<<<nsm, 256, smem_bytes>>>(
        Wsi, Wsh, b_bd, vs,
        Wmx1, Wmh1, Wih1, Whh1, b1,
        Wmx2, Wmh2, Wih2, Whh2, b2,
        out, out_size);
}

// round 10
// speedup vs baseline: 1.7064x; 1.7064x over previous
#include <cuda_runtime.h>
#include <math.h>
#include <stdint.h>

// ---------------------------------------------------------------- dims
#define Bb 128
#define Ss 512
#define Hh 1024
#define MIDm 512
#define FEATf 576
#define BH 131072      // B*H
#define BMID 65536     // B*MID
#define B4H 524288     // B*4H
#define NX 37748736    // S*FEAT*B   (X stored [t][k][b])

// ---------------------------------------------------------------- scratch
constexpr size_t OFF_X    = 0;
constexpr size_t OFF_WSI  = OFF_X + NX;                    // [576][512]
constexpr size_t OFF_WSH  = OFF_WSI + 576*512;             // [1024][512]
constexpr size_t OFF_WMX1 = OFF_WSH + 1024*512;            // [576][1024]
constexpr size_t OFF_WMH1 = OFF_WMX1 + 576*1024;           // [1024][1024]
constexpr size_t OFF_WIH1 = OFF_WMH1 + 1024*1024;          // [576][4096]
constexpr size_t OFF_WHH1 = OFF_WIH1 + (size_t)576*4096;   // [1024][4096]
constexpr size_t OFF_WMX2 = OFF_WHH1 + (size_t)1024*4096;  // [1024][1024]
constexpr size_t OFF_WMH2 = OFF_WMX2 + 1024*1024;
constexpr size_t OFF_WIH2 = OFF_WMH2 + 1024*1024;          // [1024][4096]
constexpr size_t OFF_WHH2 = OFF_WIH2 + (size_t)1024*4096;  // [1024][4096]
constexpr size_t OFF_H1T  = OFF_WHH2 + (size_t)1024*4096;  // [1024][128] k-major
constexpr size_t OFF_C1T  = OFF_H1T + BH;
constexpr size_t OFF_H2T  = OFF_C1T + BH;
constexpr size_t OFF_C2T  = OFF_H2T + BH;
constexpr size_t OFF_X2T  = OFF_C2T + BH;
constexpr size_t OFF_MM1  = OFF_X2T + BH;
constexpr size_t OFF_MM2  = OFF_MM1 + BH;
constexpr size_t OFF_ZBA  = OFF_MM2 + BH;          // 2 x [128][512]
constexpr size_t OFF_ZBB  = OFF_ZBA + 2*BMID;      // 4 x [128][512]
constexpr size_t OFF_M1A  = OFF_ZBB + 4*BMID;      // 2 x [128][1024]
constexpr size_t OFF_M1B  = OFF_M1A + 2*BH;        // 4 x [128][1024]
constexpr size_t OFF_Z1A  = OFF_M1B + 4*BH;        // 2 x [128][4096]
constexpr size_t OFF_Z1B  = OFF_Z1A + 2*B4H;       // 4 x [128][4096]
constexpr size_t OFF_M2A  = OFF_Z1B + 4*B4H;       // 4 x [128][1024]
constexpr size_t OFF_M2B  = OFF_M2A + 4*BH;
constexpr size_t OFF_Z2A  = OFF_M2B + 4*BH;        // 4 x [128][4096]
constexpr size_t OFF_Z2B  = OFF_Z2A + 4*B4H;
constexpr size_t OFF_SBUF = OFF_Z2B + 4*B4H;
constexpr size_t SCRATCH_TOTAL = OFF_SBUF + 128;

__device__ __align__(16) float g_scratch[SCRATCH_TOTAL];
__device__ unsigned g_bar_count = 0;
__device__ unsigned g_bar_gen   = 0;
__device__ unsigned g_work      = 0;
__device__ float    g_flag      = 0.0f;

// ---------------------------------------------------------------- output layout
#define OUT_H2F   67108864            // B*S*H
#define OUT_C2F   (OUT_H2F + BH)
#define OUT_FLAGS (OUT_C2F + BH)

__device__ __forceinline__ float sigm(float x) { return 1.0f / (1.0f + expf(-x)); }

// ---------------------------------------------------------------- grid barrier
__device__ __forceinline__ void grid_barrier(unsigned nct)
{
    __syncthreads();
    if (threadIdx.x == 0) {
        unsigned gen = *(volatile unsigned*)&g_bar_gen;
        __threadfence();
        unsigned prev = atomicAdd(&g_bar_count, 1u);
        if (prev == nct - 1u) {
            *(volatile unsigned*)&g_work = 0u;
            *(volatile unsigned*)&g_bar_count = 0u;
            __threadfence();
            *(volatile unsigned*)&g_bar_gen = gen + 1u;
        } else {
            while (*(volatile unsigned*)&g_bar_gen == gen) { __nanosleep(64); }
        }
        __threadfence();
    }
    __syncthreads();
}

// ---------------------------------------------------------------- GEMM tile
// out[0:128, n0:n0+64] = At[k0:k0+32*nch, 0:128]^T @ Wt[k0:.., n0:n0+64]
// At k-major [K][128]; Wt k-major [K][N]; out row-major [128][N] (ldo == ldw).
// 256 threads; per-thread 8(m)x4(n) via packed f32x2; cp.async double buffer.
// smem: A bufs 2x4096 floats @0, W bufs 2x2048 floats @8192.
__device__ __forceinline__ void cp16(uint32_t dst, const float* src) {
    asm volatile("cp.async.cg.shared.global [%0], [%1], 16;" :: "r"(dst), "l"(src));
}

__device__ void gemm_tile(float* smemf, uint32_t smemu,
                          const float* __restrict__ At,
                          const float* __restrict__ Wt, int ldw,
                          int k0, int nch, int n0,
                          float* __restrict__ outp)
{
    const int tid = threadIdx.x;
    const int tm = tid >> 4, tn = tid & 15;

    unsigned long long acc[16];
#pragma unroll
    for (int i = 0; i < 16; i++) acc[i] = 0ull;

    auto copy_chunk = [&](int c) {
        const int buf = c & 1;
        const float* As = At + (size_t)(k0 + c * 32) * 128;
        uint32_t adst = smemu + buf * 16384;
#pragma unroll
        for (int p = 0; p < 4; p++)
            cp16(adst + (p * 256 + tid) * 16, As + (p * 256 + tid) * 4);
        const float* Ws = Wt + (size_t)(k0 + c * 32) * ldw + n0;
        uint32_t wdst = smemu + 32768 + buf * 8192;
#pragma unroll
        for (int p = 0; p < 2; p++) {
            int r = (tid >> 4) + p * 16;
            cp16(wdst + (r * 64 + (tid & 15) * 4) * 4, Ws + (size_t)r * ldw + (tid & 15) * 4);
        }
        asm volatile("cp.async.commit_group;");
    };

    copy_chunk(0);
    for (int c = 0; c < nch; c++) {
        if (c + 1 < nch) { copy_chunk(c + 1); asm volatile("cp.async.wait_group 1;"); }
        else             { asm volatile("cp.async.wait_group 0;"); }
        __syncthreads();
        const float* cA = smemf + (c & 1) * 4096;
        const float* cW = smemf + 8192 + (c & 1) * 2048;
#pragma unroll 8
        for (int k = 0; k < 32; k++) {
            ulonglong2 Alo = *(const ulonglong2*)(cA + k * 128 + tm * 8);
            ulonglong2 Ahi = *(const ulonglong2*)(cA + k * 128 + tm * 8 + 4);
            float4 w = *(const float4*)(cW + k * 64 + tn * 4);
            unsigned long long w0, w1, w2, w3;
            asm("mov.b64 %0,{%1,%1};" : "=l"(w0) : "r"(__float_as_uint(w.x)));
            asm("mov.b64 %0,{%1,%1};" : "=l"(w1) : "r"(__float_as_uint(w.y)));
            asm("mov.b64 %0,{%1,%1};" : "=l"(w2) : "r"(__float_as_uint(w.z)));
            asm("mov.b64 %0,{%1,%1};" : "=l"(w3) : "r"(__float_as_uint(w.w)));
#define FX2(i, a, b) asm("fma.rn.f32x2 %0, %1, %2, %0;" : "+l"(acc[i]) : "l"(a), "l"(b))
            FX2(0,  Alo.x, w0); FX2(1,  Alo.x, w1); FX2(2,  Alo.x, w2); FX2(3,  Alo.x, w3);
            FX2(4,  Alo.y, w0); FX2(5,  Alo.y, w1); FX2(6,  Alo.y, w2); FX2(7,  Alo.y, w3);
            FX2(8,  Ahi.x, w0); FX2(9,  Ahi.x, w1); FX2(10, Ahi.x, w2); FX2(11, Ahi.x, w3);
            FX2(12, Ahi.y, w0); FX2(13, Ahi.y, w1); FX2(14, Ahi.y, w2); FX2(15, Ahi.y, w3);
#undef FX2
        }
        __syncthreads();
    }

#pragma unroll
    for (int r = 0; r < 4; r++) {
        uint32_t l0,h0,l1,h1,l2,h2,l3,h3;
        asm("mov.b64 {%0,%1},%2;" : "=r"(l0), "=r"(h0) : "l"(acc[r*4+0]));
        asm("mov.b64 {%0,%1},%2;" : "=r"(l1), "=r"(h1) : "l"(acc[r*4+1]));
        asm("mov.b64 {%0,%1},%2;" : "=r"(l2), "=r"(h2) : "l"(acc[r*4+2]));
        asm("mov.b64 {%0,%1},%2;" : "=r"(l3), "=r"(h3) : "l"(acc[r*4+3]));
        *(float4*)&outp[(size_t)(tm*8 + r*2    ) * ldw + n0 + tn*4] =
            make_float4(__uint_as_float(l0), __uint_as_float(l1), __uint_as_float(l2), __uint_as_float(l3));
        *(float4*)&outp[(size_t)(tm*8 + r*2 + 1) * ldw + n0 + tn*4] =
            make_float4(__uint_as_float(h0), __uint_as_float(h1), __uint_as_float(h2), __uint_as_float(h3));
    }
}

// ---------------------------------------------------------------- persistent kernel
__global__ void __launch_bounds__(256, 2)
enc_persistent(const float* __restrict__ b_bd, const float* __restrict__ vs,
               const float* __restrict__ b1,   const float* __restrict__ b2,
               float* __restrict__ out, int out_size)
{
    extern __shared__ float smemf[];
    const uint32_t smemu = (uint32_t)__cvta_generic_to_shared(smemf);
    __shared__ int s_id;

    const unsigned nct = gridDim.x;
    const int bid = blockIdx.x, tid = threadIdx.x;
    float* base = g_scratch;

    float* h1t = base + OFF_H1T;  float* c1t = base + OFF_C1T;
    float* h2t = base + OFF_H2T;  float* c2t = base + OFF_C2T;
    float* x2t = base + OFF_X2T;
    float* mm1 = base + OFF_MM1;  float* mm2 = base + OFF_MM2;
    float* sbuf = base + OFF_SBUF;

#define GRAB_TILE(id_)  { if (tid == 0) s_id = (int)atomicAdd(&g_work, 1u); \
                          __syncthreads(); (id_) = s_id; __syncthreads(); }

    // zero recurrent state (h1t,c1t,h2t,c2t contiguous)
    for (int i = bid * 256 + tid; i < 4 * BH; i += nct * 256) h1t[i] = 0.0f;
    grid_barrier(nct);

    for (int t = 0; t < Ss; t++) {
        const float* xt = base + OFF_X + (size_t)t * FEATf * Bb;

        // ---- Phase A : 272 tiles ----
        for (;;) {
            int id; GRAB_TILE(id);
            if (id >= 272) break;
            if (id < 16) {
                int hf = id >> 3, j = id & 7;
                gemm_tile(smemf, smemu, xt, base + OFF_WSI, 512, hf*288, 9, j*64, base + OFF_ZBA + (size_t)hf*BMID);
            } else if (id < 48) {
                int i2 = id - 16, q = i2 >> 3, j = i2 & 7;
                gemm_tile(smemf, smemu, h1t, base + OFF_WSH, 512, q*256, 8, j*64, base + OFF_ZBB + (size_t)q*BMID);
            } else if (id < 80) {
                int i2 = id - 48, hf = i2 >> 4, j = i2 & 15;
                gemm_tile(smemf, smemu, xt, base + OFF_WMX1, 1024, hf*288, 9, j*64, base + OFF_M1A + (size_t)hf*BH);
            } else if (id < 144) {
                int i2 = id - 80, q = i2 >> 4, j = i2 & 15;
                gemm_tile(smemf, smemu, h1t, base + OFF_WMH1, 1024, q*256, 8, j*64, base + OFF_M1B + (size_t)q*BH);
            } else {
                int i2 = id - 144, hf = i2 >> 6, j = i2 & 63;
                gemm_tile(smemf, smemu, xt, base + OFF_WIH1, 4096, hf*288, 9, j*64, base + OFF_Z1A + (size_t)hf*B4H);
            }
        }
        grid_barrier(nct);

        // ---- Phase A2 : combine mm1 + boundary ----
        {
            const float* m1a0 = base + OFF_M1A;           const float* m1a1 = m1a0 + BH;
            const float* m1b0 = base + OFF_M1B;           const float* m1b1 = m1b0 + BH;
            const float* m1b2 = m1b0 + 2*BH;              const float* m1b3 = m1b0 + 3*BH;
            for (int idx = bid * 256 + tid; idx < BH; idx += nct * 256) {
                int b = idx >> 10, h = idx & 1023;
                size_t s = (size_t)b * 1024 + h;
                float ma = m1a0[s] + m1a1[s];
                float mb = m1b0[s] + m1b1[s] + m1b2[s] + m1b3[s];
                mm1[h * 128 + b] = ma * mb;
            }
            if (bid < 16) {
                const float* za0 = base + OFF_ZBA; const float* za1 = za0 + BMID;
                const float* zb0 = base + OFF_ZBB; const float* zb1 = zb0 + BMID;
                const float* zb2 = zb0 + 2*BMID;   const float* zb3 = zb0 + 3*BMID;
                int w = tid >> 5, lane = tid & 31;
                int b = bid * 8 + w;
                float sum = 0.0f;
                for (int j = lane; j < MIDm; j += 32) {
                    size_t s = (size_t)b * 512 + j;
                    float z = za0[s] + za1[s] + zb0[s] + zb1[s] + zb2[s] + zb3[s] + b_bd[j];
                    sum += z * vs[j];
                }
#pragma unroll
                for (int o = 16; o > 0; o >>= 1) sum += __shfl_down_sync(0xffffffffu, sum, o);
                if (lane == 0) {
                    float p = 1.0f / (1.0f + expf(-sum));
                    float bin = (p > 0.5f) ? 1.0f : 0.0f;
                    float sv = p + (bin - p);
                    sbuf[b] = sv;
                    if (b == 0) {
                        g_flag = sv;
                        if (OUT_FLAGS + t < out_size) out[OUT_FLAGS + t] = sv;
                    }
                }
            }
        }
        grid_barrier(nct);

        // ---- Phase B : 256 tiles (z1b = mm1 @ Whh1^T, 4-way split-K) ----
        for (;;) {
            int id; GRAB_TILE(id);
            if (id >= 256) break;
            int q = id >> 6, j = id & 63;
            gemm_tile(smemf, smemu, mm1, base + OFF_WHH1, 4096, q*256, 8, j*64, base + OFF_Z1B + (size_t)q*B4H);
        }
        grid_barrier(nct);

        // ---- Phase C : gates1 ----
        {
            const float* za0 = base + OFF_Z1A; const float* za1 = za0 + B4H;
            const float* zb0 = base + OFF_Z1B; const float* zb1 = zb0 + B4H;
            const float* zb2 = zb0 + 2*B4H;    const float* zb3 = zb0 + 3*B4H;
            for (int idx = bid * 256 + tid; idx < BH; idx += nct * 256) {
                int b = idx >> 10, h = idx & 1023;
                size_t zi = (size_t)b * 4096 + h;
#define GSUM(g) (za0[zi+(g)*1024]+za1[zi+(g)*1024]+zb0[zi+(g)*1024]+zb1[zi+(g)*1024]+zb2[zi+(g)*1024]+zb3[zi+(g)*1024]+b1[(g)*1024+h])
                float iz = GSUM(0), fz = GSUM(1), gz = GSUM(2), oz = GSUM(3);
#undef GSUM
                int s = h * 128 + b;
                float cn = sigm(fz) * c1t[s] + sigm(iz) * tanhf(gz);
                float hn = sigm(oz) * tanhf(cn);
                float sv = sbuf[b];
                float om = 1.0f - sv;
                x2t[s] = hn * sv;
                h1t[s] = hn * om;
                c1t[s] = cn * om;
            }
        }
        grid_barrier(nct);

        const float fl = *(volatile float*)&g_flag;

        if (fl > 0.5f) {
            // ---- Phase D : 384 tiles ----
            for (;;) {
                int id; GRAB_TILE(id);
                if (id >= 384) break;
                if (id < 64) {
                    int q = id >> 4, j = id & 15;
                    gemm_tile(smemf, smemu, x2t, base + OFF_WMX2, 1024, q*256, 8, j*64, base + OFF_M2A + (size_t)q*BH);
                } else if (id < 128) {
                    int i2 = id - 64, q = i2 >> 4, j = i2 & 15;
                    gemm_tile(smemf, smemu, h2t, base + OFF_WMH2, 1024, q*256, 8, j*64, base + OFF_M2B + (size_t)q*BH);
                } else {
                    int i2 = id - 128, q = i2 >> 6, j = i2 & 63;
                    gemm_tile(smemf, smemu, x2t, base + OFF_WIH2, 4096, q*256, 8, j*64, base + OFF_Z2A + (size_t)q*B4H);
                }
            }
            grid_barrier(nct);

            // ---- Phase D2 : combine mm2 ----
            {
                const float* a0 = base + OFF_M2A; const float* a1 = a0 + BH;
                const float* a2 = a0 + 2*BH;      const float* a3 = a0 + 3*BH;
                const float* e0 = base + OFF_M2B; const float* e1 = e0 + BH;
                const float* e2 = e0 + 2*BH;      const float* e3 = e0 + 3*BH;
                for (int idx = bid * 256 + tid; idx < BH; idx += nct * 256) {
                    int b = idx >> 10, h = idx & 1023;
                    size_t s = (size_t)b * 1024 + h;
                    float ma = a0[s] + a1[s] + a2[s] + a3[s];
                    float mb = e0[s] + e1[s] + e2[s] + e3[s];
                    mm2[h * 128 + b] = ma * mb;
                }
            }
            grid_barrier(nct);

            // ---- Phase E : 256 tiles ----
            for (;;) {
                int id; GRAB_TILE(id);
                if (id >= 256) break;
                int q = id >> 6, j = id & 63;
                gemm_tile(smemf, smemu, mm2, base + OFF_WHH2, 4096, q*256, 8, j*64, base + OFF_Z2B + (size_t)q*B4H);
            }
            grid_barrier(nct);
        }

        // ---- Phase F : gates2 / copy ----
        {
            const float* za0 = base + OFF_Z2A; const float* za1 = za0 + B4H;
            const float* za2 = za0 + 2*B4H;    const float* za3 = za0 + 3*B4H;
            const float* zb0 = base + OFF_Z2B; const float* zb1 = zb0 + B4H;
            const float* zb2 = zb0 + 2*B4H;    const float* zb3 = zb0 + 3*B4H;
            for (int idx = bid * 256 + tid; idx < BH; idx += nct * 256) {
                int b = idx >> 10, h = idx & 1023;
                size_t oidx = (size_t)b * Ss * Hh + (size_t)t * Hh + h;
                int s = h * 128 + b;
                if (fl > 0.5f) {
                    size_t zi = (size_t)b * 4096 + h;
#define GSUM(g) (za0[zi+(g)*1024]+za1[zi+(g)*1024]+za2[zi+(g)*1024]+za3[zi+(g)*1024]+ \
                 zb0[zi+(g)*1024]+zb1[zi+(g)*1024]+zb2[zi+(g)*1024]+zb3[zi+(g)*1024]+b2[(g)*1024+h])
                    float iz = GSUM(0), fz = GSUM(1), gz = GSUM(2), oz = GSUM(3);
#undef GSUM
                    float cn = sigm(fz) * c2t[s] + sigm(iz) * tanhf(gz);
                    float hn = sigm(oz) * tanhf(cn);
                    h2t[s] = hn;
                    c2t[s] = cn;
                    out[oidx] = hn;
                } else {
                    out[oidx] = h2t[s];
                }
            }
        }
        grid_barrier(nct);
    }

    // ---- tail: final states ----
    for (int idx = bid * 256 + tid; idx < BH; idx += nct * 256) {
        int b = idx >> 10, h = idx & 1023;
        int s = h * 128 + b;
        if (OUT_H2F + idx < out_size) out[OUT_H2F + (size_t)b * 1024 + h] = h2t[s];
        if (OUT_C2F + idx < out_size) out[OUT_C2F + (size_t)b * 1024 + h] = c2t[s];
    }
#undef GRAB_TILE
}

// ---------------------------------------------------------------- weight transpose
// src [N][K] row-major  ->  dst [K][N]
__global__ void transpose_kernel(const float* __restrict__ src, float* __restrict__ dst,
                                 int N, int K)
{
    __shared__ float tile[32][33];
    int kb = blockIdx.x * 32, nb = blockIdx.y * 32;
    int tx = threadIdx.x, ty = threadIdx.y;
#pragma unroll
    for (int r = 0; r < 4; r++)
        tile[ty + r * 8][tx] = src[(size_t)(nb + ty + r * 8) * K + kb + tx];
    __syncthreads();
#pragma unroll
    for (int r = 0; r < 4; r++)
        dst[(size_t)(kb + ty + r * 8) * N + nb + tx] = tile[tx][ty + r * 8];
}

// ---------------------------------------------------------------- embedding gather
// X[t][f][b] (k-major per timestep)
__global__ void gather_kernel(const int* __restrict__ enc, const int* __restrict__ xenc,
                              const float* __restrict__ wemb, const float* __restrict__ xemb,
                              float* __restrict__ X)
{
    int t = blockIdx.x, b = blockIdx.y, tid = threadIdx.x;
    __shared__ int sid, sxid;
    if (tid == 0) { sid = enc[b * Ss + t]; sxid = xenc[b * Ss + t]; }
    __syncthreads();
    int id = sid, xid = sxid;
    float* dst = X + (size_t)t * FEATf * Bb + b;
    for (int f = tid; f < 512; f += 128)
        dst[(size_t)f * 128] = wemb[(size_t)id * 512 + f];
    int f = 512 + tid;
    if (f < 576)
        dst[(size_t)f * 128] = xemb[xid * 64 + (f - 512)];
}

// ----------------------------------------------------------------
extern "C" void kernel_launch(void* const* d_in, const int* in_sizes, int n_in,
                              void* d_out, int out_size)
{
    const int*   enc  = (const int*)d_in[0];
    const int*   xenc = (const int*)d_in[1];
    const float* wemb = (const float*)d_in[2];
    const float* xemb = (const float*)d_in[3];
    const float* Wsi  = (const float*)d_in[4];
    const float* Wsh  = (const float*)d_in[5];
    const float* b_bd = (const float*)d_in[6];
    const float* vs   = (const float*)d_in[7];
    const float* Wmx1 = (const float*)d_in[8];
    const float* Wmh1 = (const float*)d_in[9];
    const float* Wih1 = (const float*)d_in[10];
    const float* Whh1 = (const float*)d_in[11];
    const float* b1   = (const float*)d_in[12];
    const float* Wmx2 = (const float*)d_in[13];
    const float* Wmh2 = (const float*)d_in[14];
    const float* Wih2 = (const float*)d_in[15];
    const float* Whh2 = (const float*)d_in[16];
    const float* b2   = (const float*)d_in[17];
    float* out = (float*)d_out;

    float* base = nullptr;
    cudaGetSymbolAddress((void**)&base, g_scratch);

    // one-time gather (re-done every replay; deterministic)
    gather_kernel<<<dim3(Ss, Bb), 128>>>(enc, xenc, wemb, xemb, base + OFF_X);

    // one-time weight transposes: src [N][K] -> dst [K][N]
    struct TJ { const float* src; size_t dst; int N, K; };
    TJ jobs[10] = {
        { Wsi,  OFF_WSI,  512,  576  },
        { Wsh,  OFF_WSH,  512,  1024 },
        { Wmx1, OFF_WMX1, 1024, 576  },
        { Wmh1, OFF_WMH1, 1024, 1024 },
        { Wih1, OFF_WIH1, 4096, 576  },
        { Whh1, OFF_WHH1, 4096, 1024 },
        { Wmx2, OFF_WMX2, 1024, 1024 },
        { Wmh2, OFF_WMH2, 1024, 1024 },
        { Wih2, OFF_WIH2, 4096, 1024 },
        { Whh2, OFF_WHH2, 4096, 1024 },
    };
    for (int i = 0; i < 10; i++)
        transpose_kernel<<<dim3(jobs[i].K / 32, jobs[i].N / 32), dim3(32, 8)>>>(
            jobs[i].src, base + jobs[i].dst, jobs[i].N, jobs[i].K);

    int nsm = 148;
    cudaDeviceGetAttribute(&nsm, cudaDevAttrMultiProcessorCount, 0);

    const int smem_bytes = (2 * 4096 + 2 * 2048) * 4;  // 49152
    cudaFuncSetAttribute(enc_persistent, cudaFuncAttributeMaxDynamicSharedMemorySize, smem_bytes);

    int occ = 1;
    cudaOccupancyMaxActiveBlocksPerMultiprocessor(&occ, enc_persistent, 256, smem_bytes);
    if (occ < 1) occ = 1;
    if (occ > 2) occ = 2;

    enc_persistent<<<nsm * occ, 256, smem_bytes>>>(b_bd, vs, b1, b2, out, out_size);
}